// round 9
// baseline (speedup 1.0000x reference)
#include <cuda_runtime.h>
#include <cuda_bf16.h>
#include <math.h>
#include <stdint.h>

#define BATCH 16
#define DIM   256
#define HH    56
#define WW    56
#define HWSZ  3136          // 56*56
#define EMB   288
#define ATTN  128
#define GRPS  32            // DIM/SP
#define EPSB  1e-5f
#define BKK   16
#define BNT   112           // 3136 = 28 * 112, no n-edge predicates

// -------------------- scratch (allocation-free: __device__ globals) --------
__device__ float g_k   [(size_t)BATCH * DIM * HWSZ];
__device__ float g_w1  [(size_t)BATCH * 128 * HWSZ];
__device__ float g_w2  [(size_t)BATCH * EMB * HWSZ];
__device__ float g_xq  [(size_t)BATCH * DIM * HWSZ];
__device__ float g_y   [(size_t)BATCH * DIM * HWSZ];
__device__ float g_col [(size_t)BATCH * 4 * 576 * HWSZ];   // im2col for grouped conv
__device__ float g_gn  [BATCH * GRPS * 2];
__device__ float g_gap [BATCH * DIM];
__device__ float g_att [BATCH * DIM * 2];

// ---------------------------------------------------------------------------
__device__ __forceinline__ uint32_t f2tf32(float v) {
    uint32_t u;
    asm("cvt.rna.tf32.f32 %0, %1;" : "=r"(u) : "f"(v));
    return u;
}
__device__ __forceinline__ void mma_tf32(float* c, const uint32_t* a, const uint32_t* b) {
    asm volatile(
        "mma.sync.aligned.m16n8k8.row.col.f32.tf32.tf32.f32 "
        "{%0,%1,%2,%3}, {%4,%5,%6,%7}, {%8,%9}, {%0,%1,%2,%3};\n"
        : "+f"(c[0]), "+f"(c[1]), "+f"(c[2]), "+f"(c[3])
        : "r"(a[0]), "r"(a[1]), "r"(a[2]), "r"(a[3]), "r"(b[0]), "r"(b[1]));
}
__device__ __forceinline__ void cpa16(float* dst, const float* src, bool pred) {
    uint32_t d = (uint32_t)__cvta_generic_to_shared(dst);
    int sz = pred ? 16 : 0;
    asm volatile("cp.async.cg.shared.global [%0], [%1], 16, %2;\n"
                 :: "r"(d), "l"(src), "r"(sz));
}
__device__ __forceinline__ void cp_commit() {
    asm volatile("cp.async.commit_group;\n");
}
template<int N> __device__ __forceinline__ void cp_wait() {
    asm volatile("cp.async.wait_group %0;\n" :: "n"(N));
}

// ---------------------------------------------------------------------------
// Double-buffered cp.async tf32 GEMM:  O[b, m, p] = sum_k W[m,k] * X(b,k,p)
//   MODE 0 : X rows are channels of X1 (XC channels)
//   MODE 1 : concat(X1 [Csplit], X2 [XC-Csplit])
//   MODE 2 : X1 = im2col buffer; B row base = blockIdx.x * 576 (group)
//   EPI  0 : BN + ReLU    EPI 1 : BN    EPI 2 : +bias
// 256 threads = 8 warps, warp grid (BM/WM) x (BN/WN), BK = 16, BN = 112.
// ---------------------------------------------------------------------------
template<int BM, int WM, int WN, int MODE, int EPI>
__global__ void __launch_bounds__(256)
convmma(const float* __restrict__ Wt,
        const float* __restrict__ X1,
        const float* __restrict__ X2,
        float* __restrict__ Out,
        int M, int Ktot, int XC, int Csplit,
        const float* __restrict__ p0,
        const float* __restrict__ p1,
        const float* __restrict__ p2,
        const float* __restrict__ p3)
{
    constexpr int BN = BNT;
    constexpr int WARPS_N = BN / WN;
    constexpr int MT = WM / 16;
    constexpr int NT = WN / 8;
    constexpr int ACH = (BM * BKK) / (4 * 256);   // A 16B-chunks per thread

    const int b    = blockIdx.z;
    const int m0   = blockIdx.x * BM;
    const int n0   = blockIdx.y * BN;
    const int tid  = threadIdx.x;
    const int wid  = tid >> 5;
    const int lane = tid & 31;
    const int grp  = lane >> 2;
    const int tg   = lane & 3;
    const int warp_m = wid / WARPS_N;
    const int warp_n = wid % WARPS_N;

    __shared__ float As[2][BM][20];        // stride 20: conflict-free, 16B aligned
    __shared__ float Bs[2][BKK][BN + 8];   // stride 120: conflict-free, 16B aligned

    float acc[MT][NT][4];
#pragma unroll
    for (int i = 0; i < MT; i++)
#pragma unroll
        for (int j = 0; j < NT; j++)
#pragma unroll
            for (int q = 0; q < 4; q++) acc[i][j][q] = 0.f;

    auto loadA = [&](int s, int k0) {
#pragma unroll
        for (int it = 0; it < ACH; it++) {
            int idx = tid + it * 256;      // over BM * 4 chunks
            int m = idx >> 2, kq = idx & 3;
            int gm = m0 + m;
            cpa16(&As[s][m][kq * 4], Wt + (size_t)gm * Ktot + k0 + kq * 4, gm < M);
        }
    };
    auto loadB = [&](int s, int k0) {
#pragma unroll
        for (int it = 0; it < 2; it++) {
            int idx = tid + it * 256;      // over 16 * 28 = 448 chunks
            if (idx < BKK * (BN / 4)) {
                int kk = idx / (BN / 4);
                int nq = idx % (BN / 4);
                int gk = k0 + kk;
                int gn = n0 + nq * 4;
                const float* src;
                if (MODE == 0)
                    src = X1 + ((size_t)b * XC + gk) * HWSZ + gn;
                else if (MODE == 1)
                    src = (gk < Csplit)
                        ? X1 + ((size_t)b * Csplit + gk) * HWSZ + gn
                        : X2 + ((size_t)b * (XC - Csplit) + (gk - Csplit)) * HWSZ + gn;
                else
                    src = X1 + ((size_t)b * XC + blockIdx.x * 576 + gk) * HWSZ + gn;
                cpa16(&Bs[s][kk][nq * 4], src, true);
            }
        }
    };

    loadA(0, 0); loadB(0, 0); cp_commit();

    const int niter = Ktot / BKK;
    for (int i = 0; i < niter; i++) {
        if (i + 1 < niter) {
            int s = (i + 1) & 1;
            loadA(s, (i + 1) * BKK); loadB(s, (i + 1) * BKK); cp_commit();
            cp_wait<1>();
        } else {
            cp_wait<0>();
        }
        __syncthreads();

        const int s = i & 1;
#pragma unroll
        for (int ks = 0; ks < BKK; ks += 8) {
            uint32_t af[MT][4];
            uint32_t bf[NT][2];
#pragma unroll
            for (int ii = 0; ii < MT; ii++) {
                int m = warp_m * WM + ii * 16 + grp;
                af[ii][0] = f2tf32(As[s][m    ][ks + tg]);
                af[ii][1] = f2tf32(As[s][m + 8][ks + tg]);
                af[ii][2] = f2tf32(As[s][m    ][ks + tg + 4]);
                af[ii][3] = f2tf32(As[s][m + 8][ks + tg + 4]);
            }
#pragma unroll
            for (int j = 0; j < NT; j++) {
                int n = warp_n * WN + j * 8 + grp;
                bf[j][0] = f2tf32(Bs[s][ks + tg    ][n]);
                bf[j][1] = f2tf32(Bs[s][ks + tg + 4][n]);
            }
#pragma unroll
            for (int ii = 0; ii < MT; ii++)
#pragma unroll
                for (int j = 0; j < NT; j++)
                    mma_tf32(acc[ii][j], af[ii], bf[j]);
        }
        __syncthreads();
    }

    // ---- epilogue
#pragma unroll
    for (int i = 0; i < MT; i++) {
        int r0 = m0 + warp_m * WM + i * 16 + grp;
        int r1 = r0 + 8;
        float sc0 = 1.f, sh0 = 0.f, sc1 = 1.f, sh1 = 0.f;
        if (EPI <= 1) {
            if (r0 < M) { sc0 = p0[r0] * rsqrtf(p3[r0] + EPSB); sh0 = p1[r0] - p2[r0] * sc0; }
            if (r1 < M) { sc1 = p0[r1] * rsqrtf(p3[r1] + EPSB); sh1 = p1[r1] - p2[r1] * sc1; }
        } else {
            if (r0 < M) sh0 = p0[r0];
            if (r1 < M) sh1 = p0[r1];
        }
#pragma unroll
        for (int j = 0; j < NT; j++) {
            int n = n0 + warp_n * WN + j * 8 + 2 * tg;
            float v0 = acc[i][j][0] * sc0 + sh0;
            float v1 = acc[i][j][1] * sc0 + sh0;
            float v2 = acc[i][j][2] * sc1 + sh1;
            float v3 = acc[i][j][3] * sc1 + sh1;
            if (EPI == 0) {
                v0 = fmaxf(v0, 0.f); v1 = fmaxf(v1, 0.f);
                v2 = fmaxf(v2, 0.f); v3 = fmaxf(v3, 0.f);
            }
            if (r0 < M) *(float2*)(Out + ((size_t)b * M + r0) * HWSZ + n) = make_float2(v0, v1);
            if (r1 < M) *(float2*)(Out + ((size_t)b * M + r1) * HWSZ + n) = make_float2(v2, v3);
        }
    }
}

// ---------------------------------------------------------------------------
// im2col for grouped 3x3 conv, pad 1: col[b][g*576 + ci*9 + t][p]
// ---------------------------------------------------------------------------
__global__ void im2col_kernel(const float* __restrict__ x, float* __restrict__ col)
{
    const int p = blockIdx.x * 256 + threadIdx.x;
    if (p >= HWSZ) return;
    const int row = blockIdx.y;     // 0..2303
    const int b   = blockIdx.z;
    const int g = row / 576, r = row % 576, ci = r / 9, t = r % 9;
    const int h = p / WW + t / 3 - 1;
    const int w = p % WW + t % 3 - 1;
    float v = 0.f;
    if ((unsigned)h < (unsigned)HH && (unsigned)w < (unsigned)WW)
        v = x[((size_t)b * DIM + g * 64 + ci) * HWSZ + h * WW + w];
    col[((size_t)b * 2304 + row) * HWSZ + p] = v;
}

// ---------------------------------------------------------------------------
__global__ void gn_stats_kernel(const float* __restrict__ w2, float* __restrict__ stat)
{
    const int g = blockIdx.x, b = blockIdx.y;
    const float4* base = (const float4*)(w2 + ((size_t)b * EMB + g * 9) * HWSZ);
    const int n4 = 9 * HWSZ / 4;   // 7056

    float s = 0.f, sq = 0.f;
    for (int i = threadIdx.x; i < n4; i += 512) {
        float4 v = base[i];
        s  += v.x + v.y + v.z + v.w;
        sq += v.x * v.x + v.y * v.y + v.z * v.z + v.w * v.w;
    }
    __shared__ float sh_s[512], sh_q[512];
    sh_s[threadIdx.x] = s; sh_q[threadIdx.x] = sq;
    __syncthreads();
    for (int off = 256; off > 0; off >>= 1) {
        if (threadIdx.x < off) {
            sh_s[threadIdx.x] += sh_s[threadIdx.x + off];
            sh_q[threadIdx.x] += sh_q[threadIdx.x + off];
        }
        __syncthreads();
    }
    if (threadIdx.x == 0) {
        float n = 9.f * HWSZ;
        float mean = sh_s[0] / n;
        float var  = sh_q[0] / n - mean * mean;
        stat[(b * GRPS + g) * 2 + 0] = mean;
        stat[(b * GRPS + g) * 2 + 1] = rsqrtf(var + EPSB);
    }
}

// ---------------------------------------------------------------------------
__global__ void dynconv_kernel(const float* __restrict__ xq,
                               const float* __restrict__ w2,
                               const float* __restrict__ stat,
                               const float* __restrict__ gng,
                               const float* __restrict__ gnb,
                               const float* __restrict__ b2g,
                               const float* __restrict__ b2b,
                               const float* __restrict__ b2m,
                               const float* __restrict__ b2v,
                               float* __restrict__ y)
{
    const int b = blockIdx.z, g = blockIdx.y;
    const int p = blockIdx.x * blockDim.x + threadIdx.x;
    if (p >= HWSZ) return;
    const int h = p / WW, w = p % WW;

    const float mean = stat[(b * GRPS + g) * 2 + 0];
    const float rstd = stat[(b * GRPS + g) * 2 + 1];

    float wn[9];
#pragma unroll
    for (int t = 0; t < 9; t++) {
        int ch = g * 9 + t;
        float v = w2[((size_t)b * EMB + ch) * HWSZ + p];
        wn[t] = (v - mean) * rstd * gng[ch] + gnb[ch];
    }

#pragma unroll
    for (int s = 0; s < 8; s++) {
        int c = g * 8 + s;
        const float* xp = xq + ((size_t)b * DIM + c) * HWSZ;
        float acc = 0.f;
#pragma unroll
        for (int t = 0; t < 9; t++) {
            int hh = h + t / 3 - 1, ww2 = w + t % 3 - 1;
            if ((unsigned)hh < (unsigned)HH && (unsigned)ww2 < (unsigned)WW)
                acc += xp[hh * WW + ww2] * wn[t];
        }
        float sc = b2g[c] * rsqrtf(b2v[c] + EPSB);
        float v = acc * sc + (b2b[c] - b2m[c] * sc);
        v = v / (1.f + expf(-v));
        y[((size_t)b * DIM + c) * HWSZ + p] = v;
    }
}

// ---------------------------------------------------------------------------
__global__ void gap_kernel(const float* __restrict__ y, const float* __restrict__ k,
                           float* __restrict__ gap)
{
    const int c = blockIdx.x, b = blockIdx.y;
    const size_t base = ((size_t)b * DIM + c) * HWSZ;
    float s = 0.f;
    for (int i = threadIdx.x; i < HWSZ; i += blockDim.x)
        s += y[base + i] + k[base + i];
    __shared__ float sh[256];
    sh[threadIdx.x] = s;
    __syncthreads();
    for (int off = 128; off > 0; off >>= 1) {
        if (threadIdx.x < off) sh[threadIdx.x] += sh[threadIdx.x + off];
        __syncthreads();
    }
    if (threadIdx.x == 0) gap[b * DIM + c] = sh[0] / (float)HWSZ;
}

// ---------------------------------------------------------------------------
__global__ void attn_kernel(const float* __restrict__ gap,
                            const float* __restrict__ s1w, const float* __restrict__ s1b,
                            const float* __restrict__ s1g, const float* __restrict__ s1bb,
                            const float* __restrict__ s1m, const float* __restrict__ s1v,
                            const float* __restrict__ s2w, const float* __restrict__ s2b,
                            float* __restrict__ att)
{
    const int b = blockIdx.x;
    const int tid = threadIdx.x;
    __shared__ float sg[DIM];
    __shared__ float sa[ATTN];

    sg[tid] = gap[b * DIM + tid];
    __syncthreads();

    if (tid < ATTN) {
        float d = 0.f;
#pragma unroll 8
        for (int j = 0; j < DIM; j++) d += s1w[tid * DIM + j] * sg[j];
        d += s1b[tid];
        float sc = s1g[tid] * rsqrtf(s1v[tid] + EPSB);
        d = d * sc + (s1bb[tid] - s1m[tid] * sc);
        sa[tid] = fmaxf(d, 0.f);
    }
    __syncthreads();

    float d0 = 0.f, d1 = 0.f;
#pragma unroll 8
    for (int j = 0; j < ATTN; j++) {
        float a = sa[j];
        d0 += s2w[(2 * tid + 0) * ATTN + j] * a;
        d1 += s2w[(2 * tid + 1) * ATTN + j] * a;
    }
    d0 += s2b[2 * tid + 0];
    d1 += s2b[2 * tid + 1];
    float mx = fmaxf(d0, d1);
    float e0 = expf(d0 - mx), e1 = expf(d1 - mx);
    float inv = 1.f / (e0 + e1);
    att[(b * DIM + tid) * 2 + 0] = e0 * inv;
    att[(b * DIM + tid) * 2 + 1] = e1 * inv;
}

// ---------------------------------------------------------------------------
__global__ void out_kernel(const float* __restrict__ y, const float* __restrict__ k,
                           const float* __restrict__ att, float* __restrict__ out)
{
    size_t i4 = (size_t)blockIdx.x * blockDim.x + threadIdx.x;
    if (i4 >= (size_t)BATCH * DIM * HWSZ / 4) return;
    int bc = (int)(i4 * 4 / HWSZ);
    float a0 = att[bc * 2 + 0];
    float a1 = att[bc * 2 + 1];
    float4 yv = ((const float4*)y)[i4];
    float4 kv = ((const float4*)k)[i4];
    float4 o;
    o.x = yv.x * a0 + kv.x * a1;
    o.y = yv.y * a0 + kv.y * a1;
    o.z = yv.z * a0 + kv.z * a1;
    o.w = yv.w * a0 + kv.w * a1;
    ((float4*)out)[i4] = o;
}

// ---------------------------------------------------------------------------
extern "C" void kernel_launch(void* const* d_in, const int* in_sizes, int n_in,
                              void* d_out, int out_size)
{
    const float* x    = (const float*)d_in[0];
    const float* ke_w = (const float*)d_in[1];
    const float* ke_g = (const float*)d_in[2];
    const float* ke_b = (const float*)d_in[3];
    const float* ke_m = (const float*)d_in[4];
    const float* ke_v = (const float*)d_in[5];
    const float* e1_w = (const float*)d_in[6];
    const float* e1_g = (const float*)d_in[7];
    const float* e1_b = (const float*)d_in[8];
    const float* e1_m = (const float*)d_in[9];
    const float* e1_v = (const float*)d_in[10];
    const float* e2_w = (const float*)d_in[11];
    const float* e2_b = (const float*)d_in[12];
    const float* gng  = (const float*)d_in[13];
    const float* gnb  = (const float*)d_in[14];
    const float* c1_w = (const float*)d_in[15];
    const float* c1_g = (const float*)d_in[16];
    const float* c1_b = (const float*)d_in[17];
    const float* c1_m = (const float*)d_in[18];
    const float* c1_v = (const float*)d_in[19];
    const float* b2_g = (const float*)d_in[20];
    const float* b2_b = (const float*)d_in[21];
    const float* b2_m = (const float*)d_in[22];
    const float* b2_v = (const float*)d_in[23];
    const float* s1_w = (const float*)d_in[24];
    const float* s1_b = (const float*)d_in[25];
    const float* s1_g = (const float*)d_in[26];
    const float* s1bb = (const float*)d_in[27];
    const float* s1_m = (const float*)d_in[28];
    const float* s1_v = (const float*)d_in[29];
    const float* s2_w = (const float*)d_in[30];
    const float* s2_b = (const float*)d_in[31];
    float* out = (float*)d_out;

    float *k_, *w1_, *w2_, *xq_, *y_, *col_, *gn_, *gap_, *att_;
    cudaGetSymbolAddress((void**)&k_,   g_k);
    cudaGetSymbolAddress((void**)&w1_,  g_w1);
    cudaGetSymbolAddress((void**)&w2_,  g_w2);
    cudaGetSymbolAddress((void**)&xq_,  g_xq);
    cudaGetSymbolAddress((void**)&y_,   g_y);
    cudaGetSymbolAddress((void**)&col_, g_col);
    cudaGetSymbolAddress((void**)&gn_,  g_gn);
    cudaGetSymbolAddress((void**)&gap_, g_gap);
    cudaGetSymbolAddress((void**)&att_, g_att);

    const int NTILES = HWSZ / BNT;   // 28

    // 0) im2col for grouped conv
    im2col_kernel<<<dim3((HWSZ + 255) / 256, 2304, BATCH), 256>>>(x, col_);

    // 1) key embed: grouped 3x3 conv + BN + ReLU  (BM=64 per group)
    convmma<64, 16, 56, 2, 0><<<dim3(4, NTILES, BATCH), 256>>>(
        ke_w, col_, nullptr, k_, DIM, 576, 2304, 0, ke_g, ke_b, ke_m, ke_v);

    // 2) w1 = ReLU(BN(e1 . concat(x, k)))
    convmma<128, 32, 56, 1, 0><<<dim3(1, NTILES, BATCH), 256>>>(
        e1_w, x, k_, w1_, 128, 512, 512, 256, e1_g, e1_b, e1_m, e1_v);

    // 3) w2 = e2 . w1 + bias
    convmma<128, 32, 56, 0, 2><<<dim3(3, NTILES, BATCH), 256>>>(
        e2_w, w1_, nullptr, w2_, EMB, 128, 128, 0, e2_b, nullptr, nullptr, nullptr);

    // 4) GroupNorm stats
    gn_stats_kernel<<<dim3(GRPS, BATCH), 512>>>(w2_, gn_);

    // 5) xq = BN(c1 . x)
    convmma<128, 32, 56, 0, 1><<<dim3(2, NTILES, BATCH), 256>>>(
        c1_w, x, nullptr, xq_, DIM, DIM, DIM, 0, c1_g, c1_b, c1_m, c1_v);

    // 6) dynamic conv + BN + swish
    dynconv_kernel<<<dim3((HWSZ + 255) / 256, GRPS, BATCH), 256>>>(
        xq_, w2_, gn_, gng, gnb, b2_g, b2_b, b2_m, b2_v, y_);

    // 7) gap = mean(y + k)
    gap_kernel<<<dim3(DIM, BATCH), 256>>>(y_, k_, gap_);

    // 8) split attention
    attn_kernel<<<BATCH, DIM>>>(gap_, s1_w, s1_b, s1_g, s1bb, s1_m, s1_v,
                                s2_w, s2_b, att_);

    // 9) out = y*a0 + k*a1
    size_t total4 = (size_t)BATCH * DIM * HWSZ / 4;
    out_kernel<<<(unsigned)((total4 + 255) / 256), 256>>>(y_, k_, att_, out);
}

// round 10
// speedup vs baseline: 1.0157x; 1.0157x over previous
#include <cuda_runtime.h>
#include <cuda_bf16.h>
#include <math.h>
#include <stdint.h>

#define BATCH 16
#define DIM   256
#define HH    56
#define WW    56
#define HWSZ  3136
#define EMB   288
#define ATTN  128
#define GRPS  32
#define EPSB  1e-5f
#define BKK   16
#define NTILE 25            // ceil(3136/128)

// -------------------- scratch (allocation-free) ----------------------------
__device__ float g_k   [(size_t)BATCH * DIM * HWSZ];
__device__ float g_w1  [(size_t)BATCH * 128 * HWSZ];
__device__ float g_w2  [(size_t)BATCH * EMB * HWSZ];
__device__ float g_xq  [(size_t)BATCH * DIM * HWSZ];
__device__ float g_y   [(size_t)BATCH * DIM * HWSZ];
__device__ float g_xc  [(size_t)BATCH * DIM * HWSZ];     // tf32-rounded x
__device__ float g_col [(size_t)BATCH * 4 * 576 * HWSZ]; // im2col (from g_xc)
__device__ float g_pke [147456];   // packed weights: [k8][m16][lane][4]
__device__ float g_pe1 [65536];
__device__ float g_pe2 [49152];    // padded 384 rows
__device__ float g_pc1 [65536];
__device__ float g_gn  [BATCH * GRPS * 2];
__device__ float g_gap [BATCH * DIM];
__device__ float g_att [BATCH * DIM * 2];

// ---------------------------------------------------------------------------
__device__ __forceinline__ float rnd_tf32(float v) {
    uint32_t u; asm("cvt.rna.tf32.f32 %0, %1;" : "=r"(u) : "f"(v));
    return __uint_as_float(u);
}
__device__ __forceinline__ void mma_tf32(float* c, const uint32_t* a, const uint32_t* b) {
    asm volatile(
        "mma.sync.aligned.m16n8k8.row.col.f32.tf32.tf32.f32 "
        "{%0,%1,%2,%3}, {%4,%5,%6,%7}, {%8,%9}, {%0,%1,%2,%3};\n"
        : "+f"(c[0]), "+f"(c[1]), "+f"(c[2]), "+f"(c[3])
        : "r"(a[0]), "r"(a[1]), "r"(a[2]), "r"(a[3]), "r"(b[0]), "r"(b[1]));
}
__device__ __forceinline__ void cpa16(float* dst, const float* src, bool pred) {
    uint32_t d = (uint32_t)__cvta_generic_to_shared(dst);
    int sz = pred ? 16 : 0;
    asm volatile("cp.async.cg.shared.global [%0], [%1], 16, %2;\n"
                 :: "r"(d), "l"(src), "r"(sz));
}
__device__ __forceinline__ void cp_commit() { asm volatile("cp.async.commit_group;\n"); }
template<int N> __device__ __forceinline__ void cp_wait() {
    asm volatile("cp.async.wait_group %0;\n" :: "n"(N));
}

// ---------------------------------------------------------------------------
// tf32 GEMM, pre-rounded operands, fragment-packed A:
//   O[b, m, p] = sum_k W[m,k] * X(b,k,p)
//   MODE 0: X1 channels   MODE 1: concat(X1,X2)@Csplit   MODE 2: im2col buffer
//   EPI 0: BN+ReLU  1: BN  2: +bias     CVT: round stored output to tf32
// 256 threads, 8 warps (BM/WM x 128/WN), BK=16, BN=128.
// ---------------------------------------------------------------------------
template<int BM, int WM, int WN, int MODE, int EPI, bool CVT>
__global__ void __launch_bounds__(256)
convmma(const float* __restrict__ Ap,      // packed A
        const float* __restrict__ X1, const float* __restrict__ X2,
        float* __restrict__ Out,
        int M, int Ktot, int MS, int XC, int Csplit,
        const float* __restrict__ p0, const float* __restrict__ p1,
        const float* __restrict__ p2, const float* __restrict__ p3)
{
    constexpr int BN = 128;
    constexpr int MT = WM / 16, NT = WN / 8;
    constexpr int M16 = BM / 16;
    constexpr int ACH = (2 * M16 * 32) / 256;   // 16B A-chunks per thread (>=1)

    const int b    = blockIdx.z;
    const int m0   = blockIdx.x * BM;
    const int n0   = blockIdx.y * BN;
    const int tid  = threadIdx.x;
    const int wid  = tid >> 5, lane = tid & 31;
    const int grp  = lane >> 2, tg = lane & 3;
    const int warp_m = wid / (BN / WN);
    const int warp_n = wid % (BN / WN);
    const int m16b = m0 / 16;

    __shared__ float As[2][2 * M16 * 128];   // [k8][m16][lane][4]
    __shared__ float Bs[2][BKK][BN + 8];

    float acc[MT][NT][4];
#pragma unroll
    for (int i = 0; i < MT; i++)
#pragma unroll
        for (int j = 0; j < NT; j++)
#pragma unroll
            for (int q = 0; q < 4; q++) acc[i][j][q] = 0.f;

    auto loadA = [&](int s, int k0) {
#pragma unroll
        for (int it = 0; it < ACH; it++) {
            int c = tid + it * 256;              // chunk over 2*M16*32
            int lk8 = c / (M16 * 32);
            int rem = c % (M16 * 32);
            int m16l = rem >> 5, ln = rem & 31;
            const float* src = Ap + ((((size_t)(k0 >> 3) + lk8) * MS + m16b + m16l) * 32 + ln) * 4;
            cpa16(&As[s][c * 4], src, true);
        }
    };
    auto loadB = [&](int s, int k0) {
#pragma unroll
        for (int it = 0; it < 2; it++) {
            int c = tid + it * 256;              // 512 chunks: kk x n16
            int kk = c >> 5, n16 = c & 31;
            int gk = k0 + kk, gn = n0 + n16 * 4;
            const float* src;
            if (MODE == 0)
                src = X1 + ((size_t)b * XC + gk) * HWSZ + gn;
            else if (MODE == 1)
                src = (gk < Csplit)
                    ? X1 + ((size_t)b * Csplit + gk) * HWSZ + gn
                    : X2 + ((size_t)b * (XC - Csplit) + (gk - Csplit)) * HWSZ + gn;
            else
                src = X1 + ((size_t)b * XC + blockIdx.x * 576 + gk) * HWSZ + gn;
            cpa16(&Bs[s][kk][n16 * 4], src, gn < HWSZ);
        }
    };

    loadA(0, 0); loadB(0, 0); cp_commit();

    const int niter = Ktot / BKK;
    for (int i = 0; i < niter; i++) {
        if (i + 1 < niter) {
            int s = (i + 1) & 1;
            loadA(s, (i + 1) * BKK); loadB(s, (i + 1) * BKK); cp_commit();
            cp_wait<1>();
        } else {
            cp_wait<0>();
        }
        __syncthreads();

        const int s = i & 1;
        const float4* Af = (const float4*)As[s];
#pragma unroll
        for (int ks = 0; ks < 2; ks++) {        // two k8 blocks
            uint32_t af[MT][4];
            uint32_t bf[NT][2];
#pragma unroll
            for (int ii = 0; ii < MT; ii++) {
                float4 v = Af[(ks * M16 + warp_m * MT + ii) * 32 + lane];
                af[ii][0] = __float_as_uint(v.x);
                af[ii][1] = __float_as_uint(v.y);
                af[ii][2] = __float_as_uint(v.z);
                af[ii][3] = __float_as_uint(v.w);
            }
#pragma unroll
            for (int j = 0; j < NT; j++) {
                int n = warp_n * WN + j * 8 + grp;
                bf[j][0] = __float_as_uint(Bs[s][ks * 8 + tg    ][n]);
                bf[j][1] = __float_as_uint(Bs[s][ks * 8 + tg + 4][n]);
            }
#pragma unroll
            for (int ii = 0; ii < MT; ii++)
#pragma unroll
                for (int j = 0; j < NT; j++)
                    mma_tf32(acc[ii][j], af[ii], bf[j]);
        }
        __syncthreads();
    }

    // ---- epilogue
#pragma unroll
    for (int i = 0; i < MT; i++) {
        int r0 = m0 + warp_m * WM + i * 16 + grp;
        int r1 = r0 + 8;
        float sc0 = 1.f, sh0 = 0.f, sc1 = 1.f, sh1 = 0.f;
        if (EPI <= 1) {
            if (r0 < M) { sc0 = p0[r0] * rsqrtf(p3[r0] + EPSB); sh0 = p1[r0] - p2[r0] * sc0; }
            if (r1 < M) { sc1 = p0[r1] * rsqrtf(p3[r1] + EPSB); sh1 = p1[r1] - p2[r1] * sc1; }
        } else {
            if (r0 < M) sh0 = p0[r0];
            if (r1 < M) sh1 = p0[r1];
        }
#pragma unroll
        for (int j = 0; j < NT; j++) {
            int n = n0 + warp_n * WN + j * 8 + 2 * tg;
            if (n >= HWSZ) continue;
            float v0 = acc[i][j][0] * sc0 + sh0;
            float v1 = acc[i][j][1] * sc0 + sh0;
            float v2 = acc[i][j][2] * sc1 + sh1;
            float v3 = acc[i][j][3] * sc1 + sh1;
            if (EPI == 0) {
                v0 = fmaxf(v0, 0.f); v1 = fmaxf(v1, 0.f);
                v2 = fmaxf(v2, 0.f); v3 = fmaxf(v3, 0.f);
            }
            if (CVT) {
                v0 = rnd_tf32(v0); v1 = rnd_tf32(v1);
                v2 = rnd_tf32(v2); v3 = rnd_tf32(v3);
            }
            if (r0 < M) *(float2*)(Out + ((size_t)b * M + r0) * HWSZ + n) = make_float2(v0, v1);
            if (r1 < M) *(float2*)(Out + ((size_t)b * M + r1) * HWSZ + n) = make_float2(v2, v3);
        }
    }
}

// ---------------------------------------------------------------------------
// prep: tf32-round x; pack weights into fragment order [k8][m16][lane][4]
//   row = m16*16 + lane/4 + (r&1)*8 ; col = k8*8 + lane%4 + (r>>1)*4
// ---------------------------------------------------------------------------
__global__ void prep_x_kernel(const float* __restrict__ x, float* __restrict__ xc)
{
    size_t i = (size_t)blockIdx.x * 256 + threadIdx.x;
    if (i < (size_t)BATCH * DIM * HWSZ) xc[i] = rnd_tf32(x[i]);
}
__device__ __forceinline__ void pk_dec(int j, int MS, int& row, int& col) {
    int r = j & 3, lane = (j >> 2) & 31, rest = j >> 7;
    row = (rest % MS) * 16 + (lane >> 2) + (r & 1) * 8;
    col = (rest / MS) * 8 + (lane & 3) + ((r >> 1) & 1) * 4;
}
__global__ void prep_w_kernel(const float* __restrict__ kew, const float* __restrict__ e1w,
                              const float* __restrict__ e2w, const float* __restrict__ c1w,
                              float* __restrict__ pke, float* __restrict__ pe1,
                              float* __restrict__ pe2, float* __restrict__ pc1)
{
    int i = blockIdx.x * 256 + threadIdx.x;
    int row, col;
    if (i < 147456) {                       // ke: 256 rows, K=576, MS=16
        pk_dec(i, 16, row, col);
        pke[i] = rnd_tf32(kew[(size_t)row * 576 + col]);
    } else if (i < 147456 + 65536) {        // e1: 128 rows, K=512, MS=8
        int j = i - 147456; pk_dec(j, 8, row, col);
        pe1[j] = rnd_tf32(e1w[(size_t)row * 512 + col]);
    } else if (i < 147456 + 65536 + 49152) {// e2: 384(pad) rows, K=128, MS=24
        int j = i - 147456 - 65536; pk_dec(j, 24, row, col);
        pe2[j] = (row < 288) ? rnd_tf32(e2w[(size_t)row * 128 + col]) : 0.f;
    } else if (i < 147456 + 65536 + 49152 + 65536) { // c1: 256 rows, K=256, MS=16
        int j = i - 147456 - 65536 - 49152; pk_dec(j, 16, row, col);
        pc1[j] = rnd_tf32(c1w[(size_t)row * 256 + col]);
    }
}

// ---------------------------------------------------------------------------
__global__ void im2col_kernel(const float* __restrict__ x, float* __restrict__ col)
{
    const int p = blockIdx.x * 256 + threadIdx.x;
    if (p >= HWSZ) return;
    const int row = blockIdx.y, b = blockIdx.z;
    const int g = row / 576, r = row % 576, ci = r / 9, t = r % 9;
    const int h = p / WW + t / 3 - 1;
    const int w = p % WW + t % 3 - 1;
    float v = 0.f;
    if ((unsigned)h < (unsigned)HH && (unsigned)w < (unsigned)WW)
        v = x[((size_t)b * DIM + g * 64 + ci) * HWSZ + h * WW + w];
    col[((size_t)b * 2304 + row) * HWSZ + p] = v;
}

// ---------------------------------------------------------------------------
__global__ void gn_stats_kernel(const float* __restrict__ w2, float* __restrict__ stat)
{
    const int g = blockIdx.x, b = blockIdx.y;
    const float4* base = (const float4*)(w2 + ((size_t)b * EMB + g * 9) * HWSZ);
    const int n4 = 9 * HWSZ / 4;
    float s = 0.f, sq = 0.f;
    for (int i = threadIdx.x; i < n4; i += 512) {
        float4 v = base[i];
        s  += v.x + v.y + v.z + v.w;
        sq += v.x * v.x + v.y * v.y + v.z * v.z + v.w * v.w;
    }
    __shared__ float sh_s[512], sh_q[512];
    sh_s[threadIdx.x] = s; sh_q[threadIdx.x] = sq;
    __syncthreads();
    for (int off = 256; off > 0; off >>= 1) {
        if (threadIdx.x < off) {
            sh_s[threadIdx.x] += sh_s[threadIdx.x + off];
            sh_q[threadIdx.x] += sh_q[threadIdx.x + off];
        }
        __syncthreads();
    }
    if (threadIdx.x == 0) {
        float n = 9.f * HWSZ;
        float mean = sh_s[0] / n;
        float var  = sh_q[0] / n - mean * mean;
        stat[(b * GRPS + g) * 2 + 0] = mean;
        stat[(b * GRPS + g) * 2 + 1] = rsqrtf(var + EPSB);
    }
}

// ---------------------------------------------------------------------------
__global__ void dynconv_kernel(const float* __restrict__ xq, const float* __restrict__ w2,
                               const float* __restrict__ stat,
                               const float* __restrict__ gng, const float* __restrict__ gnb,
                               const float* __restrict__ b2g, const float* __restrict__ b2b,
                               const float* __restrict__ b2m, const float* __restrict__ b2v,
                               float* __restrict__ y)
{
    const int b = blockIdx.z, g = blockIdx.y;
    const int p = blockIdx.x * blockDim.x + threadIdx.x;
    if (p >= HWSZ) return;
    const int h = p / WW, w = p % WW;
    const float mean = stat[(b * GRPS + g) * 2 + 0];
    const float rstd = stat[(b * GRPS + g) * 2 + 1];
    float wn[9];
#pragma unroll
    for (int t = 0; t < 9; t++) {
        int ch = g * 9 + t;
        float v = w2[((size_t)b * EMB + ch) * HWSZ + p];
        wn[t] = (v - mean) * rstd * gng[ch] + gnb[ch];
    }
#pragma unroll
    for (int s = 0; s < 8; s++) {
        int c = g * 8 + s;
        const float* xp = xq + ((size_t)b * DIM + c) * HWSZ;
        float acc = 0.f;
#pragma unroll
        for (int t = 0; t < 9; t++) {
            int hh = h + t / 3 - 1, ww2 = w + t % 3 - 1;
            if ((unsigned)hh < (unsigned)HH && (unsigned)ww2 < (unsigned)WW)
                acc += xp[hh * WW + ww2] * wn[t];
        }
        float sc = b2g[c] * rsqrtf(b2v[c] + EPSB);
        float v = acc * sc + (b2b[c] - b2m[c] * sc);
        v = v / (1.f + expf(-v));
        y[((size_t)b * DIM + c) * HWSZ + p] = v;
    }
}

// ---------------------------------------------------------------------------
__global__ void gap_kernel(const float* __restrict__ y, const float* __restrict__ k,
                           float* __restrict__ gap)
{
    const int c = blockIdx.x, b = blockIdx.y;
    const size_t base = ((size_t)b * DIM + c) * HWSZ;
    float s = 0.f;
    for (int i = threadIdx.x; i < HWSZ; i += blockDim.x)
        s += y[base + i] + k[base + i];
    __shared__ float sh[256];
    sh[threadIdx.x] = s;
    __syncthreads();
    for (int off = 128; off > 0; off >>= 1) {
        if (threadIdx.x < off) sh[threadIdx.x] += sh[threadIdx.x + off];
        __syncthreads();
    }
    if (threadIdx.x == 0) gap[b * DIM + c] = sh[0] / (float)HWSZ;
}

// ---------------------------------------------------------------------------
__global__ void attn_kernel(const float* __restrict__ gap,
                            const float* __restrict__ s1w, const float* __restrict__ s1b,
                            const float* __restrict__ s1g, const float* __restrict__ s1bb,
                            const float* __restrict__ s1m, const float* __restrict__ s1v,
                            const float* __restrict__ s2w, const float* __restrict__ s2b,
                            float* __restrict__ att)
{
    const int b = blockIdx.x;
    const int tid = threadIdx.x;
    __shared__ float sg[DIM];
    __shared__ float sa[ATTN];
    sg[tid] = gap[b * DIM + tid];
    __syncthreads();
    if (tid < ATTN) {
        float d = 0.f;
#pragma unroll 8
        for (int j = 0; j < DIM; j++) d += s1w[tid * DIM + j] * sg[j];
        d += s1b[tid];
        float sc = s1g[tid] * rsqrtf(s1v[tid] + EPSB);
        d = d * sc + (s1bb[tid] - s1m[tid] * sc);
        sa[tid] = fmaxf(d, 0.f);
    }
    __syncthreads();
    float d0 = 0.f, d1 = 0.f;
#pragma unroll 8
    for (int j = 0; j < ATTN; j++) {
        float a = sa[j];
        d0 += s2w[(2 * tid + 0) * ATTN + j] * a;
        d1 += s2w[(2 * tid + 1) * ATTN + j] * a;
    }
    d0 += s2b[2 * tid + 0];
    d1 += s2b[2 * tid + 1];
    float mx = fmaxf(d0, d1);
    float e0 = expf(d0 - mx), e1 = expf(d1 - mx);
    float inv = 1.f / (e0 + e1);
    att[(b * DIM + tid) * 2 + 0] = e0 * inv;
    att[(b * DIM + tid) * 2 + 1] = e1 * inv;
}

// ---------------------------------------------------------------------------
__global__ void out_kernel(const float* __restrict__ y, const float* __restrict__ k,
                           const float* __restrict__ att, float* __restrict__ out)
{
    size_t i4 = (size_t)blockIdx.x * blockDim.x + threadIdx.x;
    if (i4 >= (size_t)BATCH * DIM * HWSZ / 4) return;
    int bc = (int)(i4 * 4 / HWSZ);
    float a0 = att[bc * 2 + 0];
    float a1 = att[bc * 2 + 1];
    float4 yv = ((const float4*)y)[i4];
    float4 kv = ((const float4*)k)[i4];
    float4 o;
    o.x = yv.x * a0 + kv.x * a1;
    o.y = yv.y * a0 + kv.y * a1;
    o.z = yv.z * a0 + kv.z * a1;
    o.w = yv.w * a0 + kv.w * a1;
    ((float4*)out)[i4] = o;
}

// ---------------------------------------------------------------------------
extern "C" void kernel_launch(void* const* d_in, const int* in_sizes, int n_in,
                              void* d_out, int out_size)
{
    const float* x    = (const float*)d_in[0];
    const float* ke_w = (const float*)d_in[1];
    const float* ke_g = (const float*)d_in[2];
    const float* ke_b = (const float*)d_in[3];
    const float* ke_m = (const float*)d_in[4];
    const float* ke_v = (const float*)d_in[5];
    const float* e1_w = (const float*)d_in[6];
    const float* e1_g = (const float*)d_in[7];
    const float* e1_b = (const float*)d_in[8];
    const float* e1_m = (const float*)d_in[9];
    const float* e1_v = (const float*)d_in[10];
    const float* e2_w = (const float*)d_in[11];
    const float* e2_b = (const float*)d_in[12];
    const float* gng  = (const float*)d_in[13];
    const float* gnb  = (const float*)d_in[14];
    const float* c1_w = (const float*)d_in[15];
    const float* c1_g = (const float*)d_in[16];
    const float* c1_b = (const float*)d_in[17];
    const float* c1_m = (const float*)d_in[18];
    const float* c1_v = (const float*)d_in[19];
    const float* b2_g = (const float*)d_in[20];
    const float* b2_b = (const float*)d_in[21];
    const float* b2_m = (const float*)d_in[22];
    const float* b2_v = (const float*)d_in[23];
    const float* s1_w = (const float*)d_in[24];
    const float* s1_b = (const float*)d_in[25];
    const float* s1_g = (const float*)d_in[26];
    const float* s1bb = (const float*)d_in[27];
    const float* s1_m = (const float*)d_in[28];
    const float* s1_v = (const float*)d_in[29];
    const float* s2_w = (const float*)d_in[30];
    const float* s2_b = (const float*)d_in[31];
    float* out = (float*)d_out;

    float *k_, *w1_, *w2_, *xq_, *y_, *xc_, *col_, *pke_, *pe1_, *pe2_, *pc1_;
    float *gn_, *gap_, *att_;
    cudaGetSymbolAddress((void**)&k_,   g_k);
    cudaGetSymbolAddress((void**)&w1_,  g_w1);
    cudaGetSymbolAddress((void**)&w2_,  g_w2);
    cudaGetSymbolAddress((void**)&xq_,  g_xq);
    cudaGetSymbolAddress((void**)&y_,   g_y);
    cudaGetSymbolAddress((void**)&xc_,  g_xc);
    cudaGetSymbolAddress((void**)&col_, g_col);
    cudaGetSymbolAddress((void**)&pke_, g_pke);
    cudaGetSymbolAddress((void**)&pe1_, g_pe1);
    cudaGetSymbolAddress((void**)&pe2_, g_pe2);
    cudaGetSymbolAddress((void**)&pc1_, g_pc1);
    cudaGetSymbolAddress((void**)&gn_,  g_gn);
    cudaGetSymbolAddress((void**)&gap_, g_gap);
    cudaGetSymbolAddress((void**)&att_, g_att);

    // 0) prep: round x to tf32, pack weights
    {
        size_t tot = (size_t)BATCH * DIM * HWSZ;
        prep_x_kernel<<<(unsigned)((tot + 255) / 256), 256>>>(x, xc_);
        prep_w_kernel<<<(327680 + 255) / 256, 256>>>(ke_w, e1_w, e2_w, c1_w,
                                                     pke_, pe1_, pe2_, pc1_);
    }

    // 0b) im2col for grouped conv (from rounded x)
    im2col_kernel<<<dim3((HWSZ + 255) / 256, 2304, BATCH), 256>>>(xc_, col_);

    // 1) key embed: grouped 3x3 + BN + ReLU, output rounded (feeds e1)
    convmma<64, 32, 32, 2, 0, true><<<dim3(4, NTILE, BATCH), 256>>>(
        pke_, col_, nullptr, k_, DIM, 576, 16, 2304, 0, ke_g, ke_b, ke_m, ke_v);

    // 2) w1 = ReLU(BN(e1 . concat(xc, k))), output rounded (feeds e2)
    convmma<128, 64, 32, 1, 0, true><<<dim3(1, NTILE, BATCH), 256>>>(
        pe1_, xc_, k_, w1_, 128, 512, 8, 512, 256, e1_g, e1_b, e1_m, e1_v);

    // 3) w2 = e2 . w1 + bias
    convmma<128, 64, 32, 0, 2, false><<<dim3(3, NTILE, BATCH), 256>>>(
        pe2_, w1_, nullptr, w2_, EMB, 128, 24, 128, 0, e2_b, nullptr, nullptr, nullptr);

    // 4) GroupNorm stats
    gn_stats_kernel<<<dim3(GRPS, BATCH), 512>>>(w2_, gn_);

    // 5) xq = BN(c1 . xc)
    convmma<128, 64, 32, 0, 1, false><<<dim3(2, NTILE, BATCH), 256>>>(
        pc1_, xc_, nullptr, xq_, DIM, 256, 16, DIM, 0, c1_g, c1_b, c1_m, c1_v);

    // 6) dynamic conv + BN + swish
    dynconv_kernel<<<dim3((HWSZ + 255) / 256, GRPS, BATCH), 256>>>(
        xq_, w2_, gn_, gng, gnb, b2_g, b2_b, b2_m, b2_v, y_);

    // 7) gap = mean(y + k)
    gap_kernel<<<dim3(DIM, BATCH), 256>>>(y_, k_, gap_);

    // 8) split attention
    attn_kernel<<<BATCH, DIM>>>(gap_, s1_w, s1_b, s1_g, s1bb, s1_m, s1_v,
                                s2_w, s2_b, att_);

    // 9) out = y*a0 + k*a1
    size_t total4 = (size_t)BATCH * DIM * HWSZ / 4;
    out_kernel<<<(unsigned)((total4 + 255) / 256), 256>>>(y_, k_, att_, out);
}

// round 13
// speedup vs baseline: 1.6208x; 1.5957x over previous
#include <cuda_runtime.h>
#include <cuda_bf16.h>
#include <math.h>
#include <stdint.h>

#define BATCH 16
#define DIM   256
#define HH    56
#define WW    56
#define HWSZ  3136
#define EMB   288
#define ATTN  128
#define GRPS  32
#define EPSB  1e-5f
#define BKK   16
#define NTILE 25            // ceil(3136/128)

// -------------------- scratch (allocation-free) ----------------------------
__device__ float g_k   [(size_t)BATCH * DIM * HWSZ];
__device__ float g_w1  [(size_t)BATCH * 128 * HWSZ];
__device__ float g_w2  [(size_t)BATCH * EMB * HWSZ];
__device__ float g_xq  [(size_t)BATCH * DIM * HWSZ];
__device__ float g_y   [(size_t)BATCH * DIM * HWSZ];
__device__ float g_xc  [(size_t)BATCH * DIM * HWSZ];     // tf32-rounded x
__device__ float g_pke [147456];   // packed ke weights: [k8][m16][lane][4], k = tap*64+ci
__device__ float g_pe1 [65536];
__device__ float g_pe2 [49152];    // padded 384 rows
__device__ float g_pc1 [65536];
__device__ float g_gn  [BATCH * GRPS * 2];
__device__ float g_gap [BATCH * DIM];
__device__ float g_att [BATCH * DIM * 2];

// ---------------------------------------------------------------------------
__device__ __forceinline__ float rnd_tf32(float v) {
    uint32_t u; asm("cvt.rna.tf32.f32 %0, %1;" : "=r"(u) : "f"(v));
    return __uint_as_float(u);
}
__device__ __forceinline__ void mma_tf32(float* c, const uint32_t* a, const uint32_t* b) {
    asm volatile(
        "mma.sync.aligned.m16n8k8.row.col.f32.tf32.tf32.f32 "
        "{%0,%1,%2,%3}, {%4,%5,%6,%7}, {%8,%9}, {%0,%1,%2,%3};\n"
        : "+f"(c[0]), "+f"(c[1]), "+f"(c[2]), "+f"(c[3])
        : "r"(a[0]), "r"(a[1]), "r"(a[2]), "r"(a[3]), "r"(b[0]), "r"(b[1]));
}
__device__ __forceinline__ void cpa16(float* dst, const float* src, bool pred) {
    uint32_t d = (uint32_t)__cvta_generic_to_shared(dst);
    int sz = pred ? 16 : 0;
    asm volatile("cp.async.cg.shared.global [%0], [%1], 16, %2;\n"
                 :: "r"(d), "l"(src), "r"(sz));
}
__device__ __forceinline__ void cpa4(float* dst, const float* src, bool pred) {
    uint32_t d = (uint32_t)__cvta_generic_to_shared(dst);
    int sz = pred ? 4 : 0;
    asm volatile("cp.async.ca.shared.global [%0], [%1], 4, %2;\n"
                 :: "r"(d), "l"(src), "r"(sz));
}
__device__ __forceinline__ void cp_commit() { asm volatile("cp.async.commit_group;\n"); }
template<int N> __device__ __forceinline__ void cp_wait() {
    asm volatile("cp.async.wait_group %0;\n" :: "n"(N));
}

// ---------------------------------------------------------------------------
// tf32 GEMM, pre-rounded operands, fragment-packed A:
//   O[b, m, p] = sum_k W[m,k] * X(b,k,p)
//   MODE 0: X1 channels   MODE 1: concat(X1,X2)@Csplit
//   MODE 2: grouped 3x3 — fused shifted-x gather, K ordered tap*64+ci
//   EPI 0: BN+ReLU  1: BN  2: +bias     CVT: round stored output to tf32
// 256 threads, 8 warps (BM/WM x 128/WN), BK=16, BN=128.
// ---------------------------------------------------------------------------
template<int BM, int WM, int WN, int MODE, int EPI, bool CVT>
__global__ void __launch_bounds__(256)
convmma(const float* __restrict__ Ap,      // packed A
        const float* __restrict__ X1, const float* __restrict__ X2,
        float* __restrict__ Out,
        int M, int Ktot, int MS, int XC, int Csplit,
        const float* __restrict__ p0, const float* __restrict__ p1,
        const float* __restrict__ p2, const float* __restrict__ p3)
{
    constexpr int BN = 128;
    constexpr int MT = WM / 16, NT = WN / 8;
    constexpr int M16 = BM / 16;
    constexpr int ACH = (2 * M16 * 32) / 256;   // 16B A-chunks per thread (>=1)

    const int b    = blockIdx.z;
    const int m0   = blockIdx.x * BM;
    const int n0   = blockIdx.y * BN;
    const int tid  = threadIdx.x;
    const int wid  = tid >> 5, lane = tid & 31;
    const int grp  = lane >> 2, tg = lane & 3;
    const int warp_m = wid / (BN / WN);
    const int warp_n = wid % (BN / WN);
    const int m16b = m0 / 16;

    __shared__ float As[2][2 * M16 * 128];   // [k8][m16][lane][4]
    __shared__ float Bs[2][BKK][BN + 8];

    float acc[MT][NT][4];
#pragma unroll
    for (int i = 0; i < MT; i++)
#pragma unroll
        for (int j = 0; j < NT; j++)
#pragma unroll
            for (int q = 0; q < 4; q++) acc[i][j][q] = 0.f;

    auto loadA = [&](int s, int k0) {
#pragma unroll
        for (int it = 0; it < ACH; it++) {
            int c = tid + it * 256;              // chunk over 2*M16*32
            int lk8 = c / (M16 * 32);
            int rem = c % (M16 * 32);
            int m16l = rem >> 5, ln = rem & 31;
            const float* src = Ap + ((((size_t)(k0 >> 3) + lk8) * MS + m16b + m16l) * 32 + ln) * 4;
            cpa16(&As[s][c * 4], src, true);
        }
    };
    auto loadB = [&](int s, int k0) {
        if (MODE != 2) {
#pragma unroll
            for (int it = 0; it < 2; it++) {
                int c = tid + it * 256;          // 512 chunks: kk x n16
                int kk = c >> 5, n16 = c & 31;
                int gk = k0 + kk, gn = n0 + n16 * 4;
                const float* src;
                if (MODE == 0)
                    src = X1 + ((size_t)b * XC + gk) * HWSZ + gn;
                else
                    src = (gk < Csplit)
                        ? X1 + ((size_t)b * Csplit + gk) * HWSZ + gn
                        : X2 + ((size_t)b * (XC - Csplit) + (gk - Csplit)) * HWSZ + gn;
                cpa16(&Bs[s][kk][n16 * 4], src, gn < HWSZ);
            }
        } else {
            // tap constant within BK=16 chunk (16 | 64, k = tap*64 + ci)
            const int t  = k0 >> 6;
            const int dh = t / 3 - 1, dw = t % 3 - 1;
            const int cb = blockIdx.x * 64 + (k0 & 63);
#pragma unroll
            for (int it = 0; it < 8; it++) {
                int idx = tid + it * 256;        // 2048 elements: kk x n
                int kk = idx >> 7, n = idx & 127;
                int gn = n0 + n;
                int h = gn / WW + dh, w = gn % WW + dw;
                bool pred = gn < HWSZ && (unsigned)h < (unsigned)HH && (unsigned)w < (unsigned)WW;
                const float* src = X1 + ((size_t)b * XC + cb + kk) * HWSZ + h * WW + w;
                cpa4(&Bs[s][kk][n], src, pred);
            }
        }
    };

    loadA(0, 0); loadB(0, 0); cp_commit();

    const int niter = Ktot / BKK;
    for (int i = 0; i < niter; i++) {
        if (i + 1 < niter) {
            int s = (i + 1) & 1;
            loadA(s, (i + 1) * BKK); loadB(s, (i + 1) * BKK); cp_commit();
            cp_wait<1>();
        } else {
            cp_wait<0>();
        }
        __syncthreads();

        const int s = i & 1;
        const float4* Af = (const float4*)As[s];
#pragma unroll
        for (int ks = 0; ks < 2; ks++) {        // two k8 blocks
            uint32_t af[MT][4];
            uint32_t bf[NT][2];
#pragma unroll
            for (int ii = 0; ii < MT; ii++) {
                float4 v = Af[(ks * M16 + warp_m * MT + ii) * 32 + lane];
                af[ii][0] = __float_as_uint(v.x);
                af[ii][1] = __float_as_uint(v.y);
                af[ii][2] = __float_as_uint(v.z);
                af[ii][3] = __float_as_uint(v.w);
            }
#pragma unroll
            for (int j = 0; j < NT; j++) {
                int n = warp_n * WN + j * 8 + grp;
                bf[j][0] = __float_as_uint(Bs[s][ks * 8 + tg    ][n]);
                bf[j][1] = __float_as_uint(Bs[s][ks * 8 + tg + 4][n]);
            }
#pragma unroll
            for (int ii = 0; ii < MT; ii++)
#pragma unroll
                for (int j = 0; j < NT; j++)
                    mma_tf32(acc[ii][j], af[ii], bf[j]);
        }
        __syncthreads();
    }

    // ---- epilogue
#pragma unroll
    for (int i = 0; i < MT; i++) {
        int r0 = m0 + warp_m * WM + i * 16 + grp;
        int r1 = r0 + 8;
        float sc0 = 1.f, sh0 = 0.f, sc1 = 1.f, sh1 = 0.f;
        if (EPI <= 1) {
            if (r0 < M) { sc0 = p0[r0] * rsqrtf(p3[r0] + EPSB); sh0 = p1[r0] - p2[r0] * sc0; }
            if (r1 < M) { sc1 = p0[r1] * rsqrtf(p3[r1] + EPSB); sh1 = p1[r1] - p2[r1] * sc1; }
        } else {
            if (r0 < M) sh0 = p0[r0];
            if (r1 < M) sh1 = p0[r1];
        }
#pragma unroll
        for (int j = 0; j < NT; j++) {
            int n = n0 + warp_n * WN + j * 8 + 2 * tg;
            if (n >= HWSZ) continue;
            float v0 = acc[i][j][0] * sc0 + sh0;
            float v1 = acc[i][j][1] * sc0 + sh0;
            float v2 = acc[i][j][2] * sc1 + sh1;
            float v3 = acc[i][j][3] * sc1 + sh1;
            if (EPI == 0) {
                v0 = fmaxf(v0, 0.f); v1 = fmaxf(v1, 0.f);
                v2 = fmaxf(v2, 0.f); v3 = fmaxf(v3, 0.f);
            }
            if (CVT) {
                v0 = rnd_tf32(v0); v1 = rnd_tf32(v1);
                v2 = rnd_tf32(v2); v3 = rnd_tf32(v3);
            }
            if (r0 < M) *(float2*)(Out + ((size_t)b * M + r0) * HWSZ + n) = make_float2(v0, v1);
            if (r1 < M) *(float2*)(Out + ((size_t)b * M + r1) * HWSZ + n) = make_float2(v2, v3);
        }
    }
}

// ---------------------------------------------------------------------------
// prep: tf32-round x; pack weights into fragment order [k8][m16][lane][4]
//   row = m16*16 + lane/4 + (r&1)*8 ; col = k8*8 + lane%4 + (r>>1)*4
// ke packed K ordering: packed col c -> original col (c%64)*9 + (c/64)
// ---------------------------------------------------------------------------
__global__ void prep_x_kernel(const float* __restrict__ x, float* __restrict__ xc)
{
    size_t i = (size_t)blockIdx.x * 256 + threadIdx.x;
    if (i < (size_t)BATCH * DIM * HWSZ) xc[i] = rnd_tf32(x[i]);
}
__device__ __forceinline__ void pk_dec(int j, int MS, int& row, int& col) {
    int r = j & 3, lane = (j >> 2) & 31, rest = j >> 7;
    row = (rest % MS) * 16 + (lane >> 2) + (r & 1) * 8;
    col = (rest / MS) * 8 + (lane & 3) + ((r >> 1) & 1) * 4;
}
__global__ void prep_w_kernel(const float* __restrict__ kew, const float* __restrict__ e1w,
                              const float* __restrict__ e2w, const float* __restrict__ c1w,
                              float* __restrict__ pke, float* __restrict__ pe1,
                              float* __restrict__ pe2, float* __restrict__ pc1)
{
    int i = blockIdx.x * 256 + threadIdx.x;
    int row, col;
    if (i < 147456) {                       // ke: 256 rows, K=576, MS=16
        pk_dec(i, 16, row, col);
        int ci = col & 63, t = col >> 6;    // k = tap*64 + ci
        pke[i] = rnd_tf32(kew[(size_t)row * 576 + ci * 9 + t]);
    } else if (i < 147456 + 65536) {        // e1: 128 rows, K=512, MS=8
        int j = i - 147456; pk_dec(j, 8, row, col);
        pe1[j] = rnd_tf32(e1w[(size_t)row * 512 + col]);
    } else if (i < 147456 + 65536 + 49152) {// e2: 384(pad) rows, K=128, MS=24
        int j = i - 147456 - 65536; pk_dec(j, 24, row, col);
        pe2[j] = (row < 288) ? rnd_tf32(e2w[(size_t)row * 128 + col]) : 0.f;
    } else if (i < 147456 + 65536 + 49152 + 65536) { // c1: 256 rows, K=256, MS=16
        int j = i - 147456 - 65536 - 49152; pk_dec(j, 16, row, col);
        pc1[j] = rnd_tf32(c1w[(size_t)row * 256 + col]);
    }
}

// ---------------------------------------------------------------------------
__global__ void gn_stats_kernel(const float* __restrict__ w2, float* __restrict__ stat)
{
    const int g = blockIdx.x, b = blockIdx.y;
    const float4* base = (const float4*)(w2 + ((size_t)b * EMB + g * 9) * HWSZ);
    const int n4 = 9 * HWSZ / 4;
    float s = 0.f, sq = 0.f;
    for (int i = threadIdx.x; i < n4; i += 512) {
        float4 v = base[i];
        s  += v.x + v.y + v.z + v.w;
        sq += v.x * v.x + v.y * v.y + v.z * v.z + v.w * v.w;
    }
    __shared__ float sh_s[512], sh_q[512];
    sh_s[threadIdx.x] = s; sh_q[threadIdx.x] = sq;
    __syncthreads();
    for (int off = 256; off > 0; off >>= 1) {
        if (threadIdx.x < off) {
            sh_s[threadIdx.x] += sh_s[threadIdx.x + off];
            sh_q[threadIdx.x] += sh_q[threadIdx.x + off];
        }
        __syncthreads();
    }
    if (threadIdx.x == 0) {
        float n = 9.f * HWSZ;
        float mean = sh_s[0] / n;
        float var  = sh_q[0] / n - mean * mean;
        stat[(b * GRPS + g) * 2 + 0] = mean;
        stat[(b * GRPS + g) * 2 + 1] = rsqrtf(var + EPSB);
    }
}

// ---------------------------------------------------------------------------
__global__ void dynconv_kernel(const float* __restrict__ xq, const float* __restrict__ w2,
                               const float* __restrict__ stat,
                               const float* __restrict__ gng, const float* __restrict__ gnb,
                               const float* __restrict__ b2g, const float* __restrict__ b2b,
                               const float* __restrict__ b2m, const float* __restrict__ b2v,
                               float* __restrict__ y)
{
    const int b = blockIdx.z, g = blockIdx.y;
    const int p = blockIdx.x * blockDim.x + threadIdx.x;
    if (p >= HWSZ) return;
    const int h = p / WW, w = p % WW;
    const float mean = stat[(b * GRPS + g) * 2 + 0];
    const float rstd = stat[(b * GRPS + g) * 2 + 1];
    float wn[9];
#pragma unroll
    for (int t = 0; t < 9; t++) {
        int ch = g * 9 + t;
        float v = w2[((size_t)b * EMB + ch) * HWSZ + p];
        wn[t] = (v - mean) * rstd * gng[ch] + gnb[ch];
    }
#pragma unroll
    for (int s = 0; s < 8; s++) {
        int c = g * 8 + s;
        const float* xp = xq + ((size_t)b * DIM + c) * HWSZ;
        float acc = 0.f;
#pragma unroll
        for (int t = 0; t < 9; t++) {
            int hh = h + t / 3 - 1, ww2 = w + t % 3 - 1;
            if ((unsigned)hh < (unsigned)HH && (unsigned)ww2 < (unsigned)WW)
                acc += xp[hh * WW + ww2] * wn[t];
        }
        float sc = b2g[c] * rsqrtf(b2v[c] + EPSB);
        float v = acc * sc + (b2b[c] - b2m[c] * sc);
        v = v / (1.f + expf(-v));
        y[((size_t)b * DIM + c) * HWSZ + p] = v;
    }
}

// ---------------------------------------------------------------------------
__global__ void gap_kernel(const float* __restrict__ y, const float* __restrict__ k,
                           float* __restrict__ gap)
{
    const int c = blockIdx.x, b = blockIdx.y;
    const size_t base = ((size_t)b * DIM + c) * HWSZ;
    float s = 0.f;
    for (int i = threadIdx.x; i < HWSZ; i += blockDim.x)
        s += y[base + i] + k[base + i];
    __shared__ float sh[256];
    sh[threadIdx.x] = s;
    __syncthreads();
    for (int off = 128; off > 0; off >>= 1) {
        if (threadIdx.x < off) sh[threadIdx.x] += sh[threadIdx.x + off];
        __syncthreads();
    }
    if (threadIdx.x == 0) gap[b * DIM + c] = sh[0] / (float)HWSZ;
}

// ---------------------------------------------------------------------------
__global__ void attn_kernel(const float* __restrict__ gap,
                            const float* __restrict__ s1w, const float* __restrict__ s1b,
                            const float* __restrict__ s1g, const float* __restrict__ s1bb,
                            const float* __restrict__ s1m, const float* __restrict__ s1v,
                            const float* __restrict__ s2w, const float* __restrict__ s2b,
                            float* __restrict__ att)
{
    const int b = blockIdx.x;
    const int tid = threadIdx.x;
    __shared__ float sg[DIM];
    __shared__ float sa[ATTN];
    sg[tid] = gap[b * DIM + tid];
    __syncthreads();
    if (tid < ATTN) {
        float d = 0.f;
#pragma unroll 8
        for (int j = 0; j < DIM; j++) d += s1w[tid * DIM + j] * sg[j];
        d += s1b[tid];
        float sc = s1g[tid] * rsqrtf(s1v[tid] + EPSB);
        d = d * sc + (s1bb[tid] - s1m[tid] * sc);
        sa[tid] = fmaxf(d, 0.f);
    }
    __syncthreads();
    float d0 = 0.f, d1 = 0.f;
#pragma unroll 8
    for (int j = 0; j < ATTN; j++) {
        float a = sa[j];
        d0 += s2w[(2 * tid + 0) * ATTN + j] * a;
        d1 += s2w[(2 * tid + 1) * ATTN + j] * a;
    }
    d0 += s2b[2 * tid + 0];
    d1 += s2b[2 * tid + 1];
    float mx = fmaxf(d0, d1);
    float e0 = expf(d0 - mx), e1 = expf(d1 - mx);
    float inv = 1.f / (e0 + e1);
    att[(b * DIM + tid) * 2 + 0] = e0 * inv;
    att[(b * DIM + tid) * 2 + 1] = e1 * inv;
}

// ---------------------------------------------------------------------------
__global__ void out_kernel(const float* __restrict__ y, const float* __restrict__ k,
                           const float* __restrict__ att, float* __restrict__ out)
{
    size_t i4 = (size_t)blockIdx.x * blockDim.x + threadIdx.x;
    if (i4 >= (size_t)BATCH * DIM * HWSZ / 4) return;
    int bc = (int)(i4 * 4 / HWSZ);
    float a0 = att[bc * 2 + 0];
    float a1 = att[bc * 2 + 1];
    float4 yv = ((const float4*)y)[i4];
    float4 kv = ((const float4*)k)[i4];
    float4 o;
    o.x = yv.x * a0 + kv.x * a1;
    o.y = yv.y * a0 + kv.y * a1;
    o.z = yv.z * a0 + kv.z * a1;
    o.w = yv.w * a0 + kv.w * a1;
    ((float4*)out)[i4] = o;
}

// ---------------------------------------------------------------------------
extern "C" void kernel_launch(void* const* d_in, const int* in_sizes, int n_in,
                              void* d_out, int out_size)
{
    const float* x    = (const float*)d_in[0];
    const float* ke_w = (const float*)d_in[1];
    const float* ke_g = (const float*)d_in[2];
    const float* ke_b = (const float*)d_in[3];
    const float* ke_m = (const float*)d_in[4];
    const float* ke_v = (const float*)d_in[5];
    const float* e1_w = (const float*)d_in[6];
    const float* e1_g = (const float*)d_in[7];
    const float* e1_b = (const float*)d_in[8];
    const float* e1_m = (const float*)d_in[9];
    const float* e1_v = (const float*)d_in[10];
    const float* e2_w = (const float*)d_in[11];
    const float* e2_b = (const float*)d_in[12];
    const float* gng  = (const float*)d_in[13];
    const float* gnb  = (const float*)d_in[14];
    const float* c1_w = (const float*)d_in[15];
    const float* c1_g = (const float*)d_in[16];
    const float* c1_b = (const float*)d_in[17];
    const float* c1_m = (const float*)d_in[18];
    const float* c1_v = (const float*)d_in[19];
    const float* b2_g = (const float*)d_in[20];
    const float* b2_b = (const float*)d_in[21];
    const float* b2_m = (const float*)d_in[22];
    const float* b2_v = (const float*)d_in[23];
    const float* s1_w = (const float*)d_in[24];
    const float* s1_b = (const float*)d_in[25];
    const float* s1_g = (const float*)d_in[26];
    const float* s1bb = (const float*)d_in[27];
    const float* s1_m = (const float*)d_in[28];
    const float* s1_v = (const float*)d_in[29];
    const float* s2_w = (const float*)d_in[30];
    const float* s2_b = (const float*)d_in[31];
    float* out = (float*)d_out;

    float *k_, *w1_, *w2_, *xq_, *y_, *xc_, *pke_, *pe1_, *pe2_, *pc1_;
    float *gn_, *gap_, *att_;
    cudaGetSymbolAddress((void**)&k_,   g_k);
    cudaGetSymbolAddress((void**)&w1_,  g_w1);
    cudaGetSymbolAddress((void**)&w2_,  g_w2);
    cudaGetSymbolAddress((void**)&xq_,  g_xq);
    cudaGetSymbolAddress((void**)&y_,   g_y);
    cudaGetSymbolAddress((void**)&xc_,  g_xc);
    cudaGetSymbolAddress((void**)&pke_, g_pke);
    cudaGetSymbolAddress((void**)&pe1_, g_pe1);
    cudaGetSymbolAddress((void**)&pe2_, g_pe2);
    cudaGetSymbolAddress((void**)&pc1_, g_pc1);
    cudaGetSymbolAddress((void**)&gn_,  g_gn);
    cudaGetSymbolAddress((void**)&gap_, g_gap);
    cudaGetSymbolAddress((void**)&att_, g_att);

    // 0) prep: round x to tf32, pack weights
    {
        size_t tot = (size_t)BATCH * DIM * HWSZ;
        prep_x_kernel<<<(unsigned)((tot + 255) / 256), 256>>>(x, xc_);
        prep_w_kernel<<<(327680 + 255) / 256, 256>>>(ke_w, e1_w, e2_w, c1_w,
                                                     pke_, pe1_, pe2_, pc1_);
    }

    // 1) key embed: grouped 3x3 + BN + ReLU (fused shifted-x gather)
    convmma<64, 32, 32, 2, 0, true><<<dim3(4, NTILE, BATCH), 256>>>(
        pke_, xc_, nullptr, k_, DIM, 576, 16, DIM, 0, ke_g, ke_b, ke_m, ke_v);

    // 2) w1 = ReLU(BN(e1 . concat(xc, k))), output rounded (feeds e2)
    convmma<128, 64, 32, 1, 0, true><<<dim3(1, NTILE, BATCH), 256>>>(
        pe1_, xc_, k_, w1_, 128, 512, 8, 512, 256, e1_g, e1_b, e1_m, e1_v);

    // 3) w2 = e2 . w1 + bias
    convmma<128, 64, 32, 0, 2, false><<<dim3(3, NTILE, BATCH), 256>>>(
        pe2_, w1_, nullptr, w2_, EMB, 128, 24, 128, 0, e2_b, nullptr, nullptr, nullptr);

    // 4) GroupNorm stats
    gn_stats_kernel<<<dim3(GRPS, BATCH), 512>>>(w2_, gn_);

    // 5) xq = BN(c1 . xc)
    convmma<128, 64, 32, 0, 1, false><<<dim3(2, NTILE, BATCH), 256>>>(
        pc1_, xc_, nullptr, xq_, DIM, 256, 16, DIM, 0, c1_g, c1_b, c1_m, c1_v);

    // 6) dynamic conv + BN + swish
    dynconv_kernel<<<dim3((HWSZ + 255) / 256, GRPS, BATCH), 256>>>(
        xq_, w2_, gn_, gng, gnb, b2_g, b2_b, b2_m, b2_v, y_);

    // 7) gap = mean(y + k)
    gap_kernel<<<dim3(DIM, BATCH), 256>>>(y_, k_, gap_);

    // 8) split attention
    attn_kernel<<<BATCH, DIM>>>(gap_, s1_w, s1_b, s1_g, s1bb, s1_m, s1_v,
                                s2_w, s2_b, att_);

    // 9) out = y*a0 + k*a1
    size_t total4 = (size_t)BATCH * DIM * HWSZ / 4;
    out_kernel<<<(unsigned)((total4 + 255) / 256), 256>>>(y_, k_, att_, out);
}